// round 9
// baseline (speedup 1.0000x reference)
#include <cuda_runtime.h>
#include <cuda_fp16.h>
#include <mma.h>
#include <cstdint>

using namespace nvcuda;

// ---------------- problem constants ----------------
#define Bn 4
#define Tn 2048
#define Dn 1024
#define Hn 16
#define HDn 64
#define NTOK 8192
#define QKV_N 3072

// ---------------- scratch (device globals) ----------------
__device__ __half g_xhi[(size_t)NTOK * Dn];
__device__ __half g_xlo[(size_t)NTOK * Dn];
__device__ __half g_wqkvT_hi[(size_t)QKV_N * Dn];   // [N][K]
__device__ __half g_wqkvT_lo[(size_t)QKV_N * Dn];
__device__ __half g_wprojT_hi[(size_t)Dn * Dn];     // [N][K]
__device__ __half g_wprojT_lo[(size_t)Dn * Dn];
__device__ __half g_qkv_hi[(size_t)NTOK * QKV_N];
__device__ __half g_qkv_lo[(size_t)NTOK * QKV_N];
__device__ __half g_attn_hi[(size_t)NTOK * Dn];
__device__ __half g_attn_lo[(size_t)NTOK * Dn];

__device__ __forceinline__ uint32_t pack_h2(float a, float b) {
    __half2 h = __halves2half2(__float2half_rn(a), __float2half_rn(b));
    return *reinterpret_cast<uint32_t*>(&h);
}

// ---------------- prep kernels ----------------
__global__ void split_x_kernel(const float* __restrict__ src,
                               __half* __restrict__ hi, __half* __restrict__ lo, int n4)
{
    int i = blockIdx.x * blockDim.x + threadIdx.x;
    if (i >= n4) return;
    float4 v = reinterpret_cast<const float4*>(src)[i];
    __half h0 = __float2half_rn(v.x), h1 = __float2half_rn(v.y);
    __half h2 = __float2half_rn(v.z), h3 = __float2half_rn(v.w);
    reinterpret_cast<__half2*>(hi)[i * 2 + 0] = __halves2half2(h0, h1);
    reinterpret_cast<__half2*>(hi)[i * 2 + 1] = __halves2half2(h2, h3);
    reinterpret_cast<__half2*>(lo)[i * 2 + 0] =
        __halves2half2(__float2half_rn(v.x - __half2float(h0)),
                       __float2half_rn(v.y - __half2float(h1)));
    reinterpret_cast<__half2*>(lo)[i * 2 + 1] =
        __halves2half2(__float2half_rn(v.z - __half2float(h2)),
                       __float2half_rn(v.w - __half2float(h3)));
}

// w [K,N] fp32 -> hiT/loT [N,K] fp16
__global__ void wT_split_kernel(const float* __restrict__ w,
                                __half* __restrict__ hiT, __half* __restrict__ loT,
                                int K, int N)
{
    __shared__ float tile[32][33];
    int n0 = blockIdx.x * 32, k0 = blockIdx.y * 32;
    int tx = threadIdx.x, ty = threadIdx.y;
#pragma unroll
    for (int j = 0; j < 32; j += 8)
        tile[ty + j][tx] = w[(size_t)(k0 + ty + j) * N + n0 + tx];
    __syncthreads();
#pragma unroll
    for (int j = 0; j < 32; j += 8) {
        float v = tile[tx][ty + j];
        __half h = __float2half_rn(v);
        size_t o = (size_t)(n0 + ty + j) * K + k0 + tx;
        hiT[o] = h;
        loT[o] = __float2half_rn(v - __half2float(h));
    }
}

// ---------------- wmma GEMM (pre-split fp16) ----------------
// C[M,N] = (Ahi+Alo)[M,K] @ (Bhi+Blo)[K,N] + bias  (3-term, lo*lo dropped)
// B given pre-transposed [N][K]. CTA tile 128x128, BK=32, 8 warps (2x4),
// warp tile 64x32. Hot loop: uint4 copies + wmma only.
#define GBK 32
#define AP 40          // smem K-pitch (halfs)
#define BIASP 132
// dynamic smem layout (bytes)
#define G_AHI 0
#define G_ALO 10240
#define G_BHI 20480
#define G_BLO 30720
#define G_BIAS 40960
#define G_SCR  49408                 // 8 warps x 16x20 fp32
#define G_SMEM (G_SCR + 8 * 16 * 20 * 4)

template <bool HALF_OUT>
__global__ __launch_bounds__(256)
void gemm16p(const __half* __restrict__ Ahi_g, const __half* __restrict__ Alo_g,
             const __half* __restrict__ BThi, const __half* __restrict__ BTlo,
             const float* __restrict__ bias,
             float* __restrict__ Cf, __half* __restrict__ Chi, __half* __restrict__ Clo,
             int Kdim, int Ndim)
{
    extern __shared__ char smraw[];
    __half* Ahi = (__half*)(smraw + G_AHI);
    __half* Alo = (__half*)(smraw + G_ALO);
    __half* Bhi = (__half*)(smraw + G_BHI);
    __half* Blo = (__half*)(smraw + G_BLO);
    float* biasT = (float*)(smraw + G_BIAS);
    float* scr_all = (float*)(smraw + G_SCR);

    const int t = threadIdx.x, wid = t >> 5, lane = t & 31;
    const int wm = wid & 1, wn = wid >> 1;
    const int row0 = blockIdx.y * 128, col0 = blockIdx.x * 128;

    for (int i = t; i < 16 * 128; i += 256) {
        int r = i >> 7, c = i & 127;
        biasT[r * BIASP + c] = bias[col0 + c];
    }
    __syncthreads();

    wmma::fragment<wmma::accumulator, 16, 16, 16, float> acc[4][2];
#pragma unroll
    for (int im = 0; im < 4; im++)
#pragma unroll
        for (int jn = 0; jn < 2; jn++)
            wmma::load_matrix_sync(acc[im][jn], biasT + wn * 32 + jn * 16,
                                   BIASP, wmma::mem_row_major);

    for (int k0 = 0; k0 < Kdim; k0 += GBK) {
        // stage global loads in regs (overlaps previous chunk's MMAs)
        uint4 sa[4], sb[4];
#pragma unroll
        for (int i = 0; i < 4; i++) {
            int id = t + i * 256;
            int term = id >> 9, rem = id & 511;
            int r = rem >> 2, c8 = (rem & 3) * 8;
            const __half* src = term ? Alo_g : Ahi_g;
            sa[i] = *reinterpret_cast<const uint4*>(src + (size_t)(row0 + r) * Kdim + k0 + c8);
            const __half* srcb = term ? BTlo : BThi;
            sb[i] = *reinterpret_cast<const uint4*>(srcb + (size_t)(col0 + r) * Kdim + k0 + c8);
        }
        __syncthreads();   // previous chunk's MMAs done
#pragma unroll
        for (int i = 0; i < 4; i++) {
            int id = t + i * 256;
            int term = id >> 9, rem = id & 511;
            int r = rem >> 2, c8 = (rem & 3) * 8;
            *reinterpret_cast<uint4*>((term ? Alo : Ahi) + r * AP + c8) = sa[i];
            *reinterpret_cast<uint4*>((term ? Blo : Bhi) + r * AP + c8) = sb[i];
        }
        __syncthreads();

#pragma unroll
        for (int ks = 0; ks < GBK; ks += 16) {
            wmma::fragment<wmma::matrix_b, 16, 16, 16, __half, wmma::col_major> bh[2], bl[2];
#pragma unroll
            for (int jn = 0; jn < 2; jn++) {
                wmma::load_matrix_sync(bh[jn], Bhi + (wn * 32 + jn * 16) * AP + ks, AP);
                wmma::load_matrix_sync(bl[jn], Blo + (wn * 32 + jn * 16) * AP + ks, AP);
            }
#pragma unroll
            for (int im = 0; im < 4; im++) {
                wmma::fragment<wmma::matrix_a, 16, 16, 16, __half, wmma::row_major> ah, al;
                wmma::load_matrix_sync(ah, Ahi + (wm * 64 + im * 16) * AP + ks, AP);
                wmma::load_matrix_sync(al, Alo + (wm * 64 + im * 16) * AP + ks, AP);
#pragma unroll
                for (int jn = 0; jn < 2; jn++) {
                    wmma::mma_sync(acc[im][jn], ah, bh[jn], acc[im][jn]);
                    wmma::mma_sync(acc[im][jn], al, bh[jn], acc[im][jn]);
                    wmma::mma_sync(acc[im][jn], ah, bl[jn], acc[im][jn]);
                }
            }
        }
    }

    // epilogue via per-warp scratch (bias already folded in)
    float* scr = scr_all + wid * 16 * 20;
    const int er = lane >> 1, ec = (lane & 1) * 8;
#pragma unroll
    for (int im = 0; im < 4; im++) {
#pragma unroll
        for (int jn = 0; jn < 2; jn++) {
            wmma::store_matrix_sync(scr, acc[im][jn], 20, wmma::mem_row_major);
            __syncwarp();
            float vs[8];
#pragma unroll
            for (int e = 0; e < 8; e++) vs[e] = scr[er * 20 + ec + e];
            size_t grow = (size_t)(row0 + wm * 64 + im * 16 + er);
            int gcol = col0 + wn * 32 + jn * 16 + ec;
            if (HALF_OUT) {
                uint4 hv, lv;
                float l[8];
                __half hh[8];
#pragma unroll
                for (int e = 0; e < 8; e++) {
                    hh[e] = __float2half_rn(vs[e]);
                    l[e] = vs[e] - __half2float(hh[e]);
                }
                hv.x = pack_h2(__half2float(hh[0]), __half2float(hh[1]));
                hv.y = pack_h2(__half2float(hh[2]), __half2float(hh[3]));
                hv.z = pack_h2(__half2float(hh[4]), __half2float(hh[5]));
                hv.w = pack_h2(__half2float(hh[6]), __half2float(hh[7]));
                lv.x = pack_h2(l[0], l[1]); lv.y = pack_h2(l[2], l[3]);
                lv.z = pack_h2(l[4], l[5]); lv.w = pack_h2(l[6], l[7]);
                *reinterpret_cast<uint4*>(Chi + grow * Ndim + gcol) = hv;
                *reinterpret_cast<uint4*>(Clo + grow * Ndim + gcol) = lv;
            } else {
                *reinterpret_cast<float4*>(Cf + grow * Ndim + gcol) =
                    make_float4(vs[0], vs[1], vs[2], vs[3]);
                *reinterpret_cast<float4*>(Cf + grow * Ndim + gcol + 4) =
                    make_float4(vs[4], vs[5], vs[6], vs[7]);
            }
            __syncwarp();
        }
    }
}

// ---------------- wmma attention (pre-split fp16 inputs) ----------------
// CTA = (b,h) x 64 q rows; kv tiles of 64. S = Qh (Kh+Kl)^T (scale in exp),
// P = exp(S/8) fp16, O += P (Vh+Vl). Final O/rowsum -> hi/lo fp16.
#define HP 72
#define SP 72
// dynamic smem layout (halfs/floats)
#define A_SMEM (6 * 64 * HP * 2 + 64 * SP * 4 + 64 * 4 * 4)

__global__ __launch_bounds__(256)
void attn16p(const __half* __restrict__ qh, const __half* __restrict__ ql,
             __half* __restrict__ oh, __half* __restrict__ ol)
{
    extern __shared__ char smraw[];
    __half* Qs  = (__half*)smraw;          // [64][HP]
    __half* Khi = Qs  + 64 * HP;
    __half* Klo = Khi + 64 * HP;
    __half* Vhi = Klo + 64 * HP;
    __half* Vlo = Vhi + 64 * HP;
    __half* Ps  = Vlo + 64 * HP;
    float*  Ss  = (float*)(Ps + 64 * HP);  // [64][SP]
    float*  Lp  = Ss + 64 * SP;            // [64][4]

    const int t = threadIdx.x, wid = t >> 5;
    const int wm = wid & 1, wn = wid >> 1;
    const int bh = blockIdx.y, b = bh >> 4, h = bh & 15;
    const int qb = blockIdx.x * 64;

    const int srow = t >> 2, squad = t & 3;

    // Q tile: 64x64 halfs (hi only)
#pragma unroll
    for (int i = 0; i < 2; i++) {
        int id = t + i * 256;
        int r = id >> 3, c8 = (id & 7) * 8;
        uint4 v = *reinterpret_cast<const uint4*>(
            qh + (size_t)(b * Tn + qb + r) * QKV_N + h * HDn + c8);
        *reinterpret_cast<uint4*>(Qs + r * HP + c8) = v;
    }

    wmma::fragment<wmma::accumulator, 16, 16, 16, float> o[2];
    wmma::fill_fragment(o[0], 0.0f);
    wmma::fill_fragment(o[1], 0.0f);
    float lsum = 0.0f;

    for (int kv0 = 0; kv0 < Tn; kv0 += 64) {
        // stage K/V hi/lo loads (8 uint4/thread)
        uint4 stg[8];
#pragma unroll
        for (int i = 0; i < 8; i++) {
            int id = t + i * 256;
            int arr = id >> 9, rem = id & 511;
            int r = rem >> 3, c8 = (rem & 7) * 8;
            const __half* src = (arr & 1) ? ql : qh;
            size_t off = (size_t)(b * Tn + kv0 + r) * QKV_N +
                         ((arr >> 1) ? 2048 : 1024) + h * HDn + c8;
            stg[i] = *reinterpret_cast<const uint4*>(src + off);
        }
        __syncthreads();   // previous tile's consumers done
#pragma unroll
        for (int i = 0; i < 8; i++) {
            int id = t + i * 256;
            int arr = id >> 9, rem = id & 511;
            int r = rem >> 3, c8 = (rem & 7) * 8;
            __half* dst = (arr == 0) ? Khi : (arr == 1) ? Klo : (arr == 2) ? Vhi : Vlo;
            *reinterpret_cast<uint4*>(dst + r * HP + c8) = stg[i];
        }
        __syncthreads();

        // S = Q K^T (2-term K)
        wmma::fragment<wmma::accumulator, 16, 16, 16, float> s[2];
        wmma::fill_fragment(s[0], 0.0f);
        wmma::fill_fragment(s[1], 0.0f);
#pragma unroll
        for (int ks = 0; ks < 64; ks += 16) {
            wmma::fragment<wmma::matrix_b, 16, 16, 16, __half, wmma::col_major> kh, kl;
            wmma::load_matrix_sync(kh, Khi + (wn * 16) * HP + ks, HP);
            wmma::load_matrix_sync(kl, Klo + (wn * 16) * HP + ks, HP);
#pragma unroll
            for (int im = 0; im < 2; im++) {
                wmma::fragment<wmma::matrix_a, 16, 16, 16, __half, wmma::row_major> qa;
                wmma::load_matrix_sync(qa, Qs + (wm * 32 + im * 16) * HP + ks, HP);
                wmma::mma_sync(s[im], qa, kh, s[im]);
                wmma::mma_sync(s[im], qa, kl, s[im]);
            }
        }
#pragma unroll
        for (int im = 0; im < 2; im++)
            wmma::store_matrix_sync(Ss + (wm * 32 + im * 16) * SP + wn * 16,
                                    s[im], SP, wmma::mem_row_major);
        __syncthreads();

        // P = exp(S/8) fp16; accumulate row sum
#pragma unroll
        for (int c = 0; c < 16; c += 8) {
            float p[8];
#pragma unroll
            for (int j = 0; j < 8; j += 4) {
                float4 sv = *reinterpret_cast<const float4*>(&Ss[srow * SP + squad * 16 + c + j]);
                p[j + 0] = __expf(sv.x * 0.125f);
                p[j + 1] = __expf(sv.y * 0.125f);
                p[j + 2] = __expf(sv.z * 0.125f);
                p[j + 3] = __expf(sv.w * 0.125f);
                lsum += (p[j] + p[j + 1]) + (p[j + 2] + p[j + 3]);
            }
            uint4 pk;
            pk.x = pack_h2(p[0], p[1]); pk.y = pack_h2(p[2], p[3]);
            pk.z = pack_h2(p[4], p[5]); pk.w = pack_h2(p[6], p[7]);
            *reinterpret_cast<uint4*>(Ps + srow * HP + squad * 16 + c) = pk;
        }
        __syncthreads();

        // O += P V (2-term V)
#pragma unroll
        for (int ks = 0; ks < 64; ks += 16) {
            wmma::fragment<wmma::matrix_b, 16, 16, 16, __half, wmma::row_major> vh, vl;
            wmma::load_matrix_sync(vh, Vhi + ks * HP + wn * 16, HP);
            wmma::load_matrix_sync(vl, Vlo + ks * HP + wn * 16, HP);
#pragma unroll
            for (int im = 0; im < 2; im++) {
                wmma::fragment<wmma::matrix_a, 16, 16, 16, __half, wmma::row_major> pa;
                wmma::load_matrix_sync(pa, Ps + (wm * 32 + im * 16) * HP + ks, HP);
                wmma::mma_sync(o[im], pa, vh, o[im]);
                wmma::mma_sync(o[im], pa, vl, o[im]);
            }
        }
    }

    // finalize: O / rowsum -> hi/lo fp16
    Lp[srow * 4 + squad] = lsum;
#pragma unroll
    for (int im = 0; im < 2; im++)
        wmma::store_matrix_sync(Ss + (wm * 32 + im * 16) * SP + wn * 16,
                                o[im], SP, wmma::mem_row_major);
    __syncthreads();

    float inv_l = 1.0f / (Lp[srow * 4 + 0] + Lp[srow * 4 + 1] +
                          Lp[srow * 4 + 2] + Lp[srow * 4 + 3]);
    size_t ob = (size_t)(b * Tn + qb + srow) * Dn + h * HDn + squad * 16;
#pragma unroll
    for (int c = 0; c < 16; c += 8) {
        float v[8];
#pragma unroll
        for (int j = 0; j < 8; j++)
            v[j] = Ss[srow * SP + squad * 16 + c + j] * inv_l;
        uint4 hv, lv;
        __half hh[8];
        float l[8];
#pragma unroll
        for (int j = 0; j < 8; j++) {
            hh[j] = __float2half_rn(v[j]);
            l[j] = v[j] - __half2float(hh[j]);
        }
        hv.x = pack_h2(__half2float(hh[0]), __half2float(hh[1]));
        hv.y = pack_h2(__half2float(hh[2]), __half2float(hh[3]));
        hv.z = pack_h2(__half2float(hh[4]), __half2float(hh[5]));
        hv.w = pack_h2(__half2float(hh[6]), __half2float(hh[7]));
        lv.x = pack_h2(l[0], l[1]); lv.y = pack_h2(l[2], l[3]);
        lv.z = pack_h2(l[4], l[5]); lv.w = pack_h2(l[6], l[7]);
        *reinterpret_cast<uint4*>(oh + ob + c) = hv;
        *reinterpret_cast<uint4*>(ol + ob + c) = lv;
    }
}

// ---------------- launch ----------------
extern "C" void kernel_launch(void* const* d_in, const int* in_sizes, int n_in,
                              void* d_out, int out_size)
{
    const float* x      = (const float*)d_in[0];
    const float* w_qkv  = (const float*)d_in[1];
    const float* b_qkv  = (const float*)d_in[2];
    const float* w_proj = (const float*)d_in[3];
    const float* b_proj = (const float*)d_in[4];
    float* out = (float*)d_out;

    __half *xhi, *xlo, *wqh, *wql, *wph, *wpl, *qkh, *qkl, *ath, *atl;
    cudaGetSymbolAddress((void**)&xhi, g_xhi);
    cudaGetSymbolAddress((void**)&xlo, g_xlo);
    cudaGetSymbolAddress((void**)&wqh, g_wqkvT_hi);
    cudaGetSymbolAddress((void**)&wql, g_wqkvT_lo);
    cudaGetSymbolAddress((void**)&wph, g_wprojT_hi);
    cudaGetSymbolAddress((void**)&wpl, g_wprojT_lo);
    cudaGetSymbolAddress((void**)&qkh, g_qkv_hi);
    cudaGetSymbolAddress((void**)&qkl, g_qkv_lo);
    cudaGetSymbolAddress((void**)&ath, g_attn_hi);
    cudaGetSymbolAddress((void**)&atl, g_attn_lo);

    cudaFuncSetAttribute(gemm16p<true>,  cudaFuncAttributeMaxDynamicSharedMemorySize, G_SMEM);
    cudaFuncSetAttribute(gemm16p<false>, cudaFuncAttributeMaxDynamicSharedMemorySize, G_SMEM);
    cudaFuncSetAttribute(attn16p,        cudaFuncAttributeMaxDynamicSharedMemorySize, A_SMEM);

    // prep: split x; transpose+split weights
    split_x_kernel<<<(NTOK * Dn / 4 + 255) / 256, 256>>>(x, xhi, xlo, NTOK * Dn / 4);
    {
        dim3 g(QKV_N / 32, Dn / 32);
        wT_split_kernel<<<g, dim3(32, 8)>>>(w_qkv, wqh, wql, Dn, QKV_N);
    }
    {
        dim3 g(Dn / 32, Dn / 32);
        wT_split_kernel<<<g, dim3(32, 8)>>>(w_proj, wph, wpl, Dn, Dn);
    }

    // 1) QKV projection -> fp16 hi/lo
    {
        dim3 grid(QKV_N / 128, NTOK / 128);
        gemm16p<true><<<grid, 256, G_SMEM>>>(xhi, xlo, wqh, wql, b_qkv,
                                             nullptr, qkh, qkl, Dn, QKV_N);
    }
    // 2) attention -> fp16 hi/lo
    {
        dim3 grid(Tn / 64, Bn * Hn);
        attn16p<<<grid, 256, A_SMEM>>>(qkh, qkl, ath, atl);
    }
    // 3) output projection -> fp32 + bias
    {
        dim3 grid(Dn / 128, NTOK / 128);
        gemm16p<false><<<grid, 256, G_SMEM>>>(ath, atl, wph, wpl, b_proj,
                                              out, nullptr, nullptr, Dn, Dn);
    }
}